// round 12
// baseline (speedup 1.0000x reference)
#include <cuda_runtime.h>
#include <cuda_bf16.h>
#include <math.h>
#include <stdint.h>

#define BB  256
#define TT  168
#define INF 64
#define HH  512
#define HOR 24
#define NHID 32
#define CHAIN_BLK 64          // blocks per chain barrier

// ---------------- device scratch (no allocations allowed) ----------------
__device__ __nv_bfloat16 g_xhi[BB * TT * INF], g_xlo[BB * TT * INF];
__device__ __nv_bfloat16 g_r0hi[4][BB * HH], g_r0lo[4][BB * HH];   // h0 ring
__device__ __nv_bfloat16 g_h1hi[2][BB * HH], g_h1lo[2][BB * HH];   // h1 ping-pong
__device__ float g_part[2][NHID][BB];
__device__ unsigned g_cnt0, g_gen0;   // L0 chain barrier (z=1 blocks)
__device__ unsigned g_cnt1, g_gen1;   // L1 chain barrier (z=0 blocks)

__device__ __nv_bfloat16 g_eWih0_hi[2048 * INF], g_eWih0_lo[2048 * INF];
__device__ __nv_bfloat16 g_eWhh0_hi[2048 * HH],  g_eWhh0_lo[2048 * HH];
__device__ __nv_bfloat16 g_eWih1_hi[2048 * HH],  g_eWih1_lo[2048 * HH];
__device__ __nv_bfloat16 g_eWhh1_hi[2048 * HH],  g_eWhh1_lo[2048 * HH];
__device__ __nv_bfloat16 g_dWhh0_hi[2048 * HH],  g_dWhh0_lo[2048 * HH];
__device__ __nv_bfloat16 g_dWih1_hi[2048 * HH],  g_dWih1_lo[2048 * HH];
__device__ __nv_bfloat16 g_dWhh1_hi[2048 * HH],  g_dWhh1_lo[2048 * HH];

__device__ __forceinline__ float sigmoidf_(float x) { return 1.0f / (1.0f + expf(-x)); }

// ---------------- single fused init kernel ----------------
__device__ __forceinline__ void conv_range(const float* __restrict__ s,
                                           __nv_bfloat16* __restrict__ hi,
                                           __nv_bfloat16* __restrict__ lo,
                                           int n, int t0, int stride) {
    for (int i = t0; i < n; i += stride) {
        float v = s[i];
        __nv_bfloat16 h = __float2bfloat16(v);
        hi[i] = h;
        lo[i] = __float2bfloat16(v - __bfloat162float(h));
    }
}

__global__ void init_all_kernel(const float* x,
    const float* eWih0, const float* eWhh0, const float* eWih1, const float* eWhh1,
    const float* dWhh0, const float* dWih1, const float* dWhh1)
{
    int t0 = blockIdx.x * blockDim.x + threadIdx.x;
    int stride = gridDim.x * blockDim.x;
    if (t0 == 0) { g_cnt0 = 0; g_gen0 = 0; g_cnt1 = 0; g_gen1 = 0; }
    __nv_bfloat16 z = __float2bfloat16(0.0f);
    for (int i = t0; i < 4 * BB * HH; i += stride) {
        (&g_r0hi[0][0])[i] = z;
        (&g_r0lo[0][0])[i] = z;
    }
    for (int i = t0; i < 2 * BB * HH; i += stride) {
        (&g_h1hi[0][0])[i] = z;
        (&g_h1lo[0][0])[i] = z;
    }
    conv_range(x,     g_xhi,      g_xlo,      BB * TT * INF, t0, stride);
    conv_range(eWih0, g_eWih0_hi, g_eWih0_lo, 2048 * INF,    t0, stride);
    conv_range(eWhh0, g_eWhh0_hi, g_eWhh0_lo, 2048 * HH,     t0, stride);
    conv_range(eWih1, g_eWih1_hi, g_eWih1_lo, 2048 * HH,     t0, stride);
    conv_range(eWhh1, g_eWhh1_hi, g_eWhh1_lo, 2048 * HH,     t0, stride);
    conv_range(dWhh0, g_dWhh0_hi, g_dWhh0_lo, 2048 * HH,     t0, stride);
    conv_range(dWih1, g_dWih1_hi, g_dWih1_lo, 2048 * HH,     t0, stride);
    conv_range(dWhh1, g_dWhh1_hi, g_dWhh1_lo, 2048 * HH,     t0, stride);
}

// ---------------- PTX helpers ----------------
__device__ __forceinline__ uint32_t smem_u32(const void* p) {
    uint32_t a;
    asm("{ .reg .u64 t; cvta.to.shared.u64 t, %1; cvt.u32.u64 %0, t; }"
        : "=r"(a) : "l"(p));
    return a;
}
__device__ __forceinline__ void cpasync16(uint32_t s, const void* g) {
    asm volatile("cp.async.cg.shared.global [%0], [%1], 16;\n" :: "r"(s), "l"(g));
}
__device__ __forceinline__ void cpasync_commit() {
    asm volatile("cp.async.commit_group;\n");
}
__device__ __forceinline__ void cpasync_wait0() {
    asm volatile("cp.async.wait_group 0;\n");
}
__device__ __forceinline__ void ldm_x4(uint32_t addr, uint32_t r[4]) {
    asm volatile("ldmatrix.sync.aligned.m8n8.x4.shared.b16 {%0,%1,%2,%3}, [%4];"
                 : "=r"(r[0]), "=r"(r[1]), "=r"(r[2]), "=r"(r[3]) : "r"(addr));
}
__device__ __forceinline__ void ldm_x2(uint32_t addr, uint32_t r[2]) {
    asm volatile("ldmatrix.sync.aligned.m8n8.x2.shared.b16 {%0,%1}, [%2];"
                 : "=r"(r[0]), "=r"(r[1]) : "r"(addr));
}
__device__ __forceinline__ void mma_bf16(float d[4], const uint32_t a[4],
                                         const uint32_t b[2]) {
    asm volatile("mma.sync.aligned.m16n8k16.row.col.f32.bf16.bf16.f32 "
                 "{%0,%1,%2,%3}, {%4,%5,%6,%7}, {%8,%9}, {%0,%1,%2,%3};"
                 : "+f"(d[0]), "+f"(d[1]), "+f"(d[2]), "+f"(d[3])
                 : "r"(a[0]), "r"(a[1]), "r"(a[2]), "r"(a[3]),
                   "r"(b[0]), "r"(b[1]));
}

#define SWZ(o) ((o) ^ (((o) >> 3) & 0x70))

#define AHI_OFF 0
#define ALO_OFF 16384
#define WHI_OFF 32768
#define WLO_OFF 40960
#define BUF_BYTES 49152
#define DYN_SMEM (2 * BUF_BYTES)
#define GPAD 80

// ---------------- sync primitives ----------------
// non-blocking arrive: last block of the chain publishes the generation
__device__ __forceinline__ void chain_arrive(unsigned* cnt, unsigned* gen, unsigned& mygen) {
    mygen++;
    __syncthreads();                            // all threads' epilogue writes issued
    if (threadIdx.x == 0) {
        __threadfence();                        // release
        if (atomicAdd(cnt, 1u) == CHAIN_BLK - 1) {
            *cnt = 0;
            __threadfence();
            *(volatile unsigned*)gen = mygen;
        }
    }
    // no trailing sync: threads run ahead into next step's independent chunks
}

__device__ __forceinline__ void wait_ge(const unsigned* p, unsigned v) {
    if (threadIdx.x == 0) {
        int it = 0;
        while (*(volatile const unsigned*)p < v) {
            if (++it > 16) __nanosleep(32);
        }
        __threadfence();                        // acquire
    }
    __syncthreads();
}

// ---------------- segment / job descriptors ----------------
struct SegP {
    const __nv_bfloat16 *Ahi, *Alo; int astr;   // activations [B or x rows, K]
    const __nv_bfloat16 *Whi, *Wlo; int wstr;   // weights [2048, wstr]
    int nch;                                    // 64-wide K chunks
    const unsigned* waitp; unsigned waitv;      // producer-readiness wait
};

struct JobP {
    SegP seg[2];
    const float* bias;                    // [2048]
    __nv_bfloat16 *HoutHi, *HoutLo;       // [B*512]
    int mode;                             // 0 plain, 1 dec0, 2 dec1
    const float* partin;                  // dec0 (null for s==0)
    const unsigned* pwaitp; unsigned pwaitv;  // dec0 epilogue-only wait
    const float* Wscal;                   // dec0: dWih0 fp32 [2048]
    const float* fcb;                     // dec0
    float* outp; int out_s;               // dec0
    const float* fcW;                     // dec1
    float* partout;                       // dec1: [NHID][BB]
};

__device__ __forceinline__ void load_seg_chunk(const SegP& G, int ci, uint32_t sbuf,
                                               int hn, int bm, int tid)
{
    int ko = ci << 6;
#pragma unroll
    for (int it = 0; it < 12; it++) {
        int cc = tid + it * 256;
        if (cc < 1024) {                   // W: 2 parts x 64 rows x 8 x 16B
            int p = cc >> 9, r = (cc >> 3) & 63, k16 = cc & 7;
            int gate = r >> 4, j = r & 15;
            const __nv_bfloat16* src = (p ? G.Wlo : G.Whi) +
                (size_t)(gate * HH + hn * 16 + j) * G.wstr + ko + k16 * 8;
            cpasync16(sbuf + (p ? WLO_OFF : WHI_OFF) + SWZ(r * 128 + k16 * 16), src);
        } else {                           // A: 2 parts x 128 rows x 8 x 16B
            int aa = cc - 1024;
            int p = aa >> 10, r = (aa >> 3) & 127, k16 = aa & 7;
            const __nv_bfloat16* src = (p ? G.Alo : G.Ahi) +
                (size_t)(bm * 128 + r) * G.astr + ko + k16 * 8;
            cpasync16(sbuf + (p ? ALO_OFF : AHI_OFF) + SWZ(r * 128 + k16 * 16), src);
        }
    }
}

// ---------------- one fused LSTM step (2-segment GEMM + epilogue) ----------------
__device__ __forceinline__ void run_job(const JobP& J, float* creg,
                                        char* dsmem, float* xs,
                                        int tid, int wid, int lane,
                                        int hn, int bm)
{
    const uint32_t sb = smem_u32(dsmem);
    const int wm = (wid & 3) * 32;
    const int wn = (wid >> 2) * 32;
    const int a_row_l = (lane & 7) + 8 * ((lane >> 3) & 1);
    const int a_kb_l  = (lane >> 4) * 16;
    const int b_row_l = lane & 7;
    const int b_kb_l  = ((lane >> 3) & 1) * 16;

    float acc[2][4][4];
#pragma unroll
    for (int m = 0; m < 2; m++)
#pragma unroll
        for (int n = 0; n < 4; n++)
#pragma unroll
            for (int e = 0; e < 4; e++) acc[m][n][e] = 0.0f;

    int gchunk = 0;   // global chunk counter (buffer parity)
#pragma unroll 1
    for (int sgi = 0; sgi < 2; sgi++) {
        const SegP& G = J.seg[sgi];
        if (G.waitp) wait_ge(G.waitp, G.waitv);   // producer-readiness
        if (G.nch == 0) continue;

        load_seg_chunk(G, 0, sb + (uint32_t)(gchunk & 1) * BUF_BYTES, hn, bm, tid);
        cpasync_commit();

#pragma unroll 1
        for (int i = 0; i < G.nch; i++, gchunk++) {
            cpasync_wait0();          // chunk gchunk arrived (only group in flight)
            __syncthreads();          // visible to all; all warps past compute(gchunk-1)
            if (i + 1 < G.nch) {
                load_seg_chunk(G, i + 1, sb + (uint32_t)((gchunk + 1) & 1) * BUF_BYTES,
                               hn, bm, tid);
                cpasync_commit();
            }

            uint32_t buf = sb + (uint32_t)(gchunk & 1) * BUF_BYTES;
            uint32_t aRow[2], bRow[4];
#pragma unroll
            for (int m = 0; m < 2; m++) {
                int row = wm + m * 16 + a_row_l;
                aRow[m] = buf + row * 128 + (((row & 7) << 4) ^ a_kb_l);
            }
#pragma unroll
            for (int n = 0; n < 4; n++) {
                int row = wn + n * 8 + b_row_l;
                bRow[n] = buf + row * 128 + (((row & 7) << 4) ^ b_kb_l);
            }

#pragma unroll
            for (int ks = 0; ks < 4; ks++) {
                uint32_t kx = (uint32_t)(ks * 32);
                uint32_t ah[2][4], al[2][4], wh[4][2], wl[4][2];
#pragma unroll
                for (int m = 0; m < 2; m++) {
                    ldm_x4((aRow[m] ^ kx) + AHI_OFF, ah[m]);
                    ldm_x4((aRow[m] ^ kx) + ALO_OFF, al[m]);
                }
#pragma unroll
                for (int n = 0; n < 4; n++) {
                    ldm_x2((bRow[n] ^ kx) + WHI_OFF, wh[n]);
                    ldm_x2((bRow[n] ^ kx) + WLO_OFF, wl[n]);
                }
#pragma unroll
                for (int m = 0; m < 2; m++)
#pragma unroll
                    for (int n = 0; n < 4; n++) mma_bf16(acc[m][n], ah[m], wh[n]);
#pragma unroll
                for (int m = 0; m < 2; m++)
#pragma unroll
                    for (int n = 0; n < 4; n++) mma_bf16(acc[m][n], al[m], wh[n]);
#pragma unroll
                for (int m = 0; m < 2; m++)
#pragma unroll
                    for (int n = 0; n < 4; n++) mma_bf16(acc[m][n], ah[m], wl[n]);
            }
        }
    }

    __syncthreads();   // all MMA compute done, buffers free for epilogue use

    // decoder L0 scalar input: GEMM above never needed it — wait only here
    if (J.mode == 1) {
        if (J.pwaitp) wait_ge(J.pwaitp, J.pwaitv);
        if (tid < 128) {
            float s = 0.0f;
            if (J.partin) {
                s = J.fcb[0];
#pragma unroll
                for (int j2 = 0; j2 < NHID; j2++)
                    s += __ldcg(&J.partin[j2 * BB + bm * 128 + tid]);
                if (J.out_s >= 0 && hn == 0) J.outp[(bm * 128 + tid) * HOR + J.out_s] = s;
            }
            xs[tid] = s;
        }
    }
    __syncthreads();

    float* gsm = (float*)dsmem;
    {
        int g = lane >> 2, t = lane & 3;
#pragma unroll
        for (int m = 0; m < 2; m++)
#pragma unroll
            for (int n = 0; n < 4; n++) {
                int r0 = wm + m * 16 + g;
                int cc = wn + n * 8 + 2 * t;
                *(float2*)&gsm[r0 * GPAD + cc]       = make_float2(acc[m][n][0], acc[m][n][1]);
                *(float2*)&gsm[(r0 + 8) * GPAD + cc] = make_float2(acc[m][n][2], acc[m][n][3]);
            }
    }
    __syncthreads();

    const int j   = tid & 15;
    const int col = hn * 16 + j;
    const float bi = J.bias[col];
    const float bf = J.bias[HH + col];
    const float bg = J.bias[2 * HH + col];
    const float bo = J.bias[3 * HH + col];
    float wsi = 0, wsf = 0, wsg = 0, wso = 0;
    if (J.mode == 1) {
        wsi = J.Wscal[col]; wsf = J.Wscal[HH + col];
        wsg = J.Wscal[2 * HH + col]; wso = J.Wscal[3 * HH + col];
    }
    const float fw = (J.mode == 2) ? J.fcW[col] : 0.0f;

#pragma unroll
    for (int i = 0; i < 8; i++) {
        int r = (tid >> 4) + i * 16;
        float pi = gsm[r * GPAD + j]      + bi;
        float pf = gsm[r * GPAD + 16 + j] + bf;
        float pg = gsm[r * GPAD + 32 + j] + bg;
        float po = gsm[r * GPAD + 48 + j] + bo;
        if (J.mode == 1) {
            float xsc = xs[r];
            pi += xsc * wsi; pf += xsc * wsf; pg += xsc * wsg; po += xsc * wso;
        }
        float c = sigmoidf_(pf) * creg[i] + sigmoidf_(pi) * tanhf(pg);
        creg[i] = c;
        float h = sigmoidf_(po) * tanhf(c);
        int idx = (bm * 128 + r) * HH + col;
        __nv_bfloat16 hh = __float2bfloat16(h);
        J.HoutHi[idx] = hh;
        J.HoutLo[idx] = __float2bfloat16(h - __bfloat162float(hh));
        if (J.mode == 2) {
            float p = h * fw;
#pragma unroll
            for (int o = 1; o < 16; o <<= 1) p += __shfl_xor_sync(0xffffffffu, p, o);
            if (j == 0) J.partout[hn * BB + bm * 128 + r] = p;
        }
    }
    // chain_arrive's syncthreads protects gsm/buffers before the next job
}

// ---------------- persistent kernel: two decoupled chains, hidden waits ----------------
__global__ __launch_bounds__(256) void lstm_persist_kernel(
    const float* __restrict__ eb0, const float* __restrict__ eb1,
    const float* __restrict__ db0, const float* __restrict__ db1,
    const float* __restrict__ dWih0, const float* __restrict__ fcW,
    const float* __restrict__ fcb, float* __restrict__ out)
{
    extern __shared__ char dsmem[];
    __shared__ float xs[128];

    const int tid  = threadIdx.x;
    const int wid  = tid >> 5;
    const int lane = tid & 31;
    const int hn   = blockIdx.x;
    const int bm   = blockIdx.y;
    const int z    = blockIdx.z;   // 0: L1 chain, 1: L0 chain

    float* pp[2] = { &g_part[0][0][0], &g_part[1][0][0] };

    float creg[8];
#pragma unroll
    for (int i = 0; i < 8; i++) creg[i] = 0.0f;

    unsigned gen = 0;

    if (z == 1) {
        // ================= L0 chain (64 blocks) =================
#pragma unroll 1
        for (int t = 0; t < TT; t++) {
            JobP J{};
            // seg0: x(t)·Wih0 — x always ready; carry ring backpressure wait here
            J.seg[0] = { g_xhi + t * INF, g_xlo + t * INF, TT * INF,
                         g_eWih0_hi, g_eWih0_lo, INF, 1,
                         (t >= 4) ? &g_gen1 : nullptr, (unsigned)(t - 3) };
            // seg1: h0(t-1)·Whh0 — own chain; wait hidden behind seg0
            J.seg[1] = { g_r0hi[(t + 3) & 3], g_r0lo[(t + 3) & 3], HH,
                         g_eWhh0_hi, g_eWhh0_lo, HH, 8,
                         &g_gen0, (unsigned)t };
            J.bias = eb0;
            J.HoutHi = g_r0hi[t & 3]; J.HoutLo = g_r0lo[t & 3];
            J.mode = 0; J.out_s = -1;
            run_job(J, creg, dsmem, xs, tid, wid, lane, hn, bm);
            chain_arrive(&g_cnt0, &g_gen0, gen);    // publishes h0(t): g_gen0 = t+1
        }
        // ---- decoder L0 steps ----
#pragma unroll 1
        for (int s = 0; s < HOR; s++) {
            int u = TT + s;
            JobP J{};
            // seg0 empty; carries ring backpressure wait
            J.seg[0] = { nullptr, nullptr, 0, nullptr, nullptr, 0, 0,
                         &g_gen1, (unsigned)(u - 3) };
            // seg1: h0(u-1)·dWhh0 — own chain
            J.seg[1] = { g_r0hi[(u + 3) & 3], g_r0lo[(u + 3) & 3], HH,
                         g_dWhh0_hi, g_dWhh0_lo, HH, 8,
                         &g_gen0, (unsigned)u };
            J.bias = db0;
            J.HoutHi = g_r0hi[u & 3]; J.HoutLo = g_r0lo[u & 3];
            J.mode = 1;
            J.partin = (s == 0) ? nullptr : pp[(s - 1) & 1];
            J.pwaitp = (s == 0) ? nullptr : &g_gen1;
            J.pwaitv = (unsigned)(TT + s);          // decL1(s-1) done (epilogue dep)
            J.Wscal = dWih0; J.fcb = fcb; J.outp = out; J.out_s = s - 1;
            run_job(J, creg, dsmem, xs, tid, wid, lane, hn, bm);
            chain_arrive(&g_cnt0, &g_gen0, gen);    // g_gen0 = TT + s + 1
        }
        // ---- final output column ----
        if (hn == 0) {
            wait_ge(&g_gen1, (unsigned)(TT + HOR)); // decL1(HOR-1) done
            if (tid < 128) {
                int row = bm * 128 + tid;
                float s = fcb[0];
#pragma unroll
                for (int j2 = 0; j2 < NHID; j2++)
                    s += __ldcg(&pp[(HOR - 1) & 1][j2 * BB + row]);
                out[row * HOR + (HOR - 1)] = s;
            }
        }
    } else {
        // ================= L1 chain (64 blocks) =================
#pragma unroll 1
        for (int t = 0; t < TT; t++) {
            JobP J{};
            // seg0: h0(t)·Wih1 — cross chain (L0 runs ahead; wait ~free). K=512 -> 8 chunks
            J.seg[0] = { g_r0hi[t & 3], g_r0lo[t & 3], HH,
                         g_eWih1_hi, g_eWih1_lo, HH, 8,
                         &g_gen0, (unsigned)(t + 1) };
            // seg1: h1(t-1)·Whh1 — own chain; barrier hidden behind seg0's 8 chunks
            J.seg[1] = { g_h1hi[t & 1], g_h1lo[t & 1], HH,
                         g_eWhh1_hi, g_eWhh1_lo, HH, 8,
                         &g_gen1, (unsigned)t };
            J.bias = eb1;
            J.HoutHi = g_h1hi[(t + 1) & 1]; J.HoutLo = g_h1lo[(t + 1) & 1];
            J.mode = 0; J.out_s = -1;
            run_job(J, creg, dsmem, xs, tid, wid, lane, hn, bm);
            chain_arrive(&g_cnt1, &g_gen1, gen);    // g_gen1 = t+1
        }
        // ---- decoder L1 steps ----
#pragma unroll 1
        for (int s = 0; s < HOR; s++) {
            int u = TT + s;
            JobP J{};
            // seg0: h1(u-1)·dWhh1 — own chain (ready early)
            J.seg[0] = { g_h1hi[u & 1], g_h1lo[u & 1], HH,
                         g_dWhh1_hi, g_dWhh1_lo, HH, 8,
                         &g_gen1, (unsigned)u };
            // seg1: h0(u)·dWih1 — cross chain; decL0(s) tail hidden behind seg0
            J.seg[1] = { g_r0hi[u & 3], g_r0lo[u & 3], HH,
                         g_dWih1_hi, g_dWih1_lo, HH, 8,
                         &g_gen0, (unsigned)(u + 1) };
            J.bias = db1;
            J.HoutHi = g_h1hi[(u + 1) & 1]; J.HoutLo = g_h1lo[(u + 1) & 1];
            J.mode = 2; J.out_s = -1;
            J.fcW = fcW; J.partout = pp[s & 1];
            run_job(J, creg, dsmem, xs, tid, wid, lane, hn, bm);
            chain_arrive(&g_cnt1, &g_gen1, gen);    // g_gen1 = TT + s + 1
        }
    }
}

// ---------------- host ----------------
extern "C" void kernel_launch(void* const* d_in, const int* in_sizes, int n_in,
                              void* d_out, int out_size)
{
    const float* x     = (const float*)d_in[0];
    const float* eWih0 = (const float*)d_in[2];
    const float* eWhh0 = (const float*)d_in[3];
    const float* eb0   = (const float*)d_in[4];
    const float* eWih1 = (const float*)d_in[5];
    const float* eWhh1 = (const float*)d_in[6];
    const float* eb1   = (const float*)d_in[7];
    const float* dWih0 = (const float*)d_in[8];
    const float* dWhh0 = (const float*)d_in[9];
    const float* db0   = (const float*)d_in[10];
    const float* dWih1 = (const float*)d_in[11];
    const float* dWhh1 = (const float*)d_in[12];
    const float* db1   = (const float*)d_in[13];
    const float* fcW   = (const float*)d_in[14];
    const float* fcb   = (const float*)d_in[15];
    float* out = (float*)d_out;

    cudaFuncSetAttribute(lstm_persist_kernel,
                         cudaFuncAttributeMaxDynamicSharedMemorySize, DYN_SMEM);

    init_all_kernel<<<256, 256>>>(x, eWih0, eWhh0, eWih1, eWhh1,
                                  dWhh0, dWih1, dWhh1);

    lstm_persist_kernel<<<dim3(NHID, 2, 2), 256, DYN_SMEM>>>(
        eb0, eb1, db0, db1, dWih0, fcW, fcb, out);
}

// round 13
// speedup vs baseline: 1.0378x; 1.0378x over previous
#include <cuda_runtime.h>
#include <cuda_bf16.h>
#include <math.h>
#include <stdint.h>

#define BB  256
#define TT  168
#define INF 64
#define HH  512
#define HOR 24
#define NHID 32
#define CHAIN_BLK 64          // blocks per chain barrier
#define THREADS 512

// ---------------- device scratch (no allocations allowed) ----------------
__device__ __nv_bfloat16 g_xhi[BB * TT * INF], g_xlo[BB * TT * INF];
__device__ __nv_bfloat16 g_r0hi[4][BB * HH], g_r0lo[4][BB * HH];   // h0 ring
__device__ __nv_bfloat16 g_h1hi[2][BB * HH], g_h1lo[2][BB * HH];   // h1 ping-pong
__device__ float g_part[2][NHID][BB];
__device__ unsigned g_cnt0, g_gen0;   // L0 chain barrier (z=1 blocks)
__device__ unsigned g_cnt1, g_gen1;   // L1 chain barrier (z=0 blocks)

__device__ __nv_bfloat16 g_eWih0_hi[2048 * INF], g_eWih0_lo[2048 * INF];
__device__ __nv_bfloat16 g_eWhh0_hi[2048 * HH],  g_eWhh0_lo[2048 * HH];
__device__ __nv_bfloat16 g_eWih1_hi[2048 * HH],  g_eWih1_lo[2048 * HH];
__device__ __nv_bfloat16 g_eWhh1_hi[2048 * HH],  g_eWhh1_lo[2048 * HH];
__device__ __nv_bfloat16 g_dWhh0_hi[2048 * HH],  g_dWhh0_lo[2048 * HH];
__device__ __nv_bfloat16 g_dWih1_hi[2048 * HH],  g_dWih1_lo[2048 * HH];
__device__ __nv_bfloat16 g_dWhh1_hi[2048 * HH],  g_dWhh1_lo[2048 * HH];

__device__ __forceinline__ float sigmoidf_(float x) { return 1.0f / (1.0f + expf(-x)); }

// ---------------- single fused init kernel ----------------
__device__ __forceinline__ void conv_range(const float* __restrict__ s,
                                           __nv_bfloat16* __restrict__ hi,
                                           __nv_bfloat16* __restrict__ lo,
                                           int n, int t0, int stride) {
    for (int i = t0; i < n; i += stride) {
        float v = s[i];
        __nv_bfloat16 h = __float2bfloat16(v);
        hi[i] = h;
        lo[i] = __float2bfloat16(v - __bfloat162float(h));
    }
}

__global__ void init_all_kernel(const float* x,
    const float* eWih0, const float* eWhh0, const float* eWih1, const float* eWhh1,
    const float* dWhh0, const float* dWih1, const float* dWhh1)
{
    int t0 = blockIdx.x * blockDim.x + threadIdx.x;
    int stride = gridDim.x * blockDim.x;
    if (t0 == 0) { g_cnt0 = 0; g_gen0 = 0; g_cnt1 = 0; g_gen1 = 0; }
    __nv_bfloat16 z = __float2bfloat16(0.0f);
    for (int i = t0; i < 4 * BB * HH; i += stride) {
        (&g_r0hi[0][0])[i] = z;
        (&g_r0lo[0][0])[i] = z;
    }
    for (int i = t0; i < 2 * BB * HH; i += stride) {
        (&g_h1hi[0][0])[i] = z;
        (&g_h1lo[0][0])[i] = z;
    }
    conv_range(x,     g_xhi,      g_xlo,      BB * TT * INF, t0, stride);
    conv_range(eWih0, g_eWih0_hi, g_eWih0_lo, 2048 * INF,    t0, stride);
    conv_range(eWhh0, g_eWhh0_hi, g_eWhh0_lo, 2048 * HH,     t0, stride);
    conv_range(eWih1, g_eWih1_hi, g_eWih1_lo, 2048 * HH,     t0, stride);
    conv_range(eWhh1, g_eWhh1_hi, g_eWhh1_lo, 2048 * HH,     t0, stride);
    conv_range(dWhh0, g_dWhh0_hi, g_dWhh0_lo, 2048 * HH,     t0, stride);
    conv_range(dWih1, g_dWih1_hi, g_dWih1_lo, 2048 * HH,     t0, stride);
    conv_range(dWhh1, g_dWhh1_hi, g_dWhh1_lo, 2048 * HH,     t0, stride);
}

// ---------------- PTX helpers ----------------
__device__ __forceinline__ uint32_t smem_u32(const void* p) {
    uint32_t a;
    asm("{ .reg .u64 t; cvta.to.shared.u64 t, %1; cvt.u32.u64 %0, t; }"
        : "=r"(a) : "l"(p));
    return a;
}
__device__ __forceinline__ void cpasync16(uint32_t s, const void* g) {
    asm volatile("cp.async.cg.shared.global [%0], [%1], 16;\n" :: "r"(s), "l"(g));
}
__device__ __forceinline__ void cpasync_commit() {
    asm volatile("cp.async.commit_group;\n");
}
__device__ __forceinline__ void cpasync_wait0() {
    asm volatile("cp.async.wait_group 0;\n");
}
__device__ __forceinline__ void cpasync_wait1() {
    asm volatile("cp.async.wait_group 1;\n");
}
__device__ __forceinline__ void ldm_x4(uint32_t addr, uint32_t r[4]) {
    asm volatile("ldmatrix.sync.aligned.m8n8.x4.shared.b16 {%0,%1,%2,%3}, [%4];"
                 : "=r"(r[0]), "=r"(r[1]), "=r"(r[2]), "=r"(r[3]) : "r"(addr));
}
__device__ __forceinline__ void ldm_x2(uint32_t addr, uint32_t r[2]) {
    asm volatile("ldmatrix.sync.aligned.m8n8.x2.shared.b16 {%0,%1}, [%2];"
                 : "=r"(r[0]), "=r"(r[1]) : "r"(addr));
}
__device__ __forceinline__ void mma_bf16(float d[4], const uint32_t a[4],
                                         const uint32_t b[2]) {
    asm volatile("mma.sync.aligned.m16n8k16.row.col.f32.bf16.bf16.f32 "
                 "{%0,%1,%2,%3}, {%4,%5,%6,%7}, {%8,%9}, {%0,%1,%2,%3};"
                 : "+f"(d[0]), "+f"(d[1]), "+f"(d[2]), "+f"(d[3])
                 : "r"(a[0]), "r"(a[1]), "r"(a[2]), "r"(a[3]),
                   "r"(b[0]), "r"(b[1]));
}

#define SWZ(o) ((o) ^ (((o) >> 3) & 0x70))

#define AHI_OFF 0
#define ALO_OFF 16384
#define WHI_OFF 32768
#define WLO_OFF 40960
#define BUF_BYTES 49152
#define DYN_SMEM (3 * BUF_BYTES)
#define GPAD 80

// ---------------- sync primitives ----------------
__device__ __forceinline__ void chain_arrive(unsigned* cnt, unsigned* gen, unsigned& mygen) {
    mygen++;
    __syncthreads();                            // all threads' epilogue writes issued
    if (threadIdx.x == 0) {
        __threadfence();                        // release
        if (atomicAdd(cnt, 1u) == CHAIN_BLK - 1) {
            *cnt = 0;
            __threadfence();
            *(volatile unsigned*)gen = mygen;
        }
    }
    // no trailing sync: threads run ahead into next step's independent work
}

__device__ __forceinline__ void wait_ge(const unsigned* p, unsigned v) {
    if (threadIdx.x == 0) {
        int it = 0;
        while (*(volatile const unsigned*)p < v) {
            if (++it > 16) __nanosleep(32);
        }
        __threadfence();                        // acquire
    }
    __syncthreads();
}

// ---------------- segment / job descriptors ----------------
struct SegP {
    const __nv_bfloat16 *Ahi, *Alo; int astr;   // activations
    const __nv_bfloat16 *Whi, *Wlo; int wstr;   // weights [2048, wstr]
    int nch;                                    // 64-wide K chunks
    const unsigned* waitp; unsigned waitv;      // producer-readiness wait
};

struct JobP {
    SegP seg[2];
    const float* bias;                    // [2048]
    __nv_bfloat16 *HoutHi, *HoutLo;       // [B*512]
    int mode;                             // 0 plain, 1 dec0, 2 dec1
    const float* partin;                  // dec0 (null for s==0)
    const unsigned* pwaitp; unsigned pwaitv;  // dec0 epilogue-only wait
    const float* Wscal;                   // dec0: dWih0 fp32 [2048]
    const float* fcb;                     // dec0
    float* outp; int out_s;               // dec0
    const float* fcW;                     // dec1
    float* partout;                       // dec1: [NHID][BB]
};

__device__ __forceinline__ void load_seg_chunk(const SegP& G, int ci, uint32_t sbuf,
                                               int hn, int bm, int tid)
{
    int ko = ci << 6;
#pragma unroll
    for (int it = 0; it < 6; it++) {
        int cc = tid + it * THREADS;
        if (cc < 1024) {                   // W: 2 parts x 64 rows x 8 x 16B
            int p = cc >> 9, r = (cc >> 3) & 63, k16 = cc & 7;
            int gate = r >> 4, j = r & 15;
            const __nv_bfloat16* src = (p ? G.Wlo : G.Whi) +
                (size_t)(gate * HH + hn * 16 + j) * G.wstr + ko + k16 * 8;
            cpasync16(sbuf + (p ? WLO_OFF : WHI_OFF) + SWZ(r * 128 + k16 * 16), src);
        } else {                           // A: 2 parts x 128 rows x 8 x 16B
            int aa = cc - 1024;
            int p = aa >> 10, r = (aa >> 3) & 127, k16 = aa & 7;
            const __nv_bfloat16* src = (p ? G.Alo : G.Ahi) +
                (size_t)(bm * 128 + r) * G.astr + ko + k16 * 8;
            cpasync16(sbuf + (p ? ALO_OFF : AHI_OFF) + SWZ(r * 128 + k16 * 16), src);
        }
    }
}

// ---------------- one fused LSTM step (2-segment GEMM + epilogue) ----------------
// 512 threads, 16 warps: warp grid 4(M) x 4(N). Warp tile 32 x 16.
__device__ __forceinline__ void run_job(const JobP& J, float* creg,
                                        char* dsmem, float* xs,
                                        int tid, int wid, int lane,
                                        int hn, int bm)
{
    const uint32_t sb = smem_u32(dsmem);
    const int wm = (wid & 3) * 32;        // M offset within 128
    const int wn = (wid >> 2) * 16;       // N offset within 64
    const int a_row_l = (lane & 7) + 8 * ((lane >> 3) & 1);
    const int a_kb_l  = (lane >> 4) * 16;
    const int b_row_l = lane & 7;
    const int b_kb_l  = ((lane >> 3) & 1) * 16;

    float acc[2][2][4];
#pragma unroll
    for (int m = 0; m < 2; m++)
#pragma unroll
        for (int n = 0; n < 2; n++)
#pragma unroll
            for (int e = 0; e < 4; e++) acc[m][n][e] = 0.0f;

#pragma unroll 1
    for (int sgi = 0; sgi < 2; sgi++) {
        const SegP& G = J.seg[sgi];
        if (G.waitp) wait_ge(G.waitp, G.waitv);   // producer-readiness
        const int nch = G.nch;
        if (nch == 0) continue;

        // 3-stage pipeline: up to 2 loads in flight during compute
        load_seg_chunk(G, 0, sb, hn, bm, tid);
        cpasync_commit();
        if (nch > 1) {
            load_seg_chunk(G, 1, sb + BUF_BYTES, hn, bm, tid);
            cpasync_commit();
        }

#pragma unroll 1
        for (int i = 0; i < nch; i++) {
            if (i + 1 < nch) cpasync_wait1(); else cpasync_wait0();
            __syncthreads();          // chunk i visible; all warps past compute(i-1)
            if (i + 2 < nch) {
                load_seg_chunk(G, i + 2,
                               sb + (uint32_t)((i + 2) % 3) * BUF_BYTES, hn, bm, tid);
                cpasync_commit();
            }

            uint32_t buf = sb + (uint32_t)(i % 3) * BUF_BYTES;
            uint32_t aRow[2], bRow[2];
#pragma unroll
            for (int m = 0; m < 2; m++) {
                int row = wm + m * 16 + a_row_l;
                aRow[m] = buf + row * 128 + (((row & 7) << 4) ^ a_kb_l);
            }
#pragma unroll
            for (int n = 0; n < 2; n++) {
                int row = wn + n * 8 + b_row_l;
                bRow[n] = buf + row * 128 + (((row & 7) << 4) ^ b_kb_l);
            }

#pragma unroll
            for (int ks = 0; ks < 4; ks++) {
                uint32_t kx = (uint32_t)(ks * 32);
                uint32_t ah[2][4], al[2][4], wh[2][2], wl[2][2];
#pragma unroll
                for (int m = 0; m < 2; m++) {
                    ldm_x4((aRow[m] ^ kx) + AHI_OFF, ah[m]);
                    ldm_x4((aRow[m] ^ kx) + ALO_OFF, al[m]);
                }
#pragma unroll
                for (int n = 0; n < 2; n++) {
                    ldm_x2((bRow[n] ^ kx) + WHI_OFF, wh[n]);
                    ldm_x2((bRow[n] ^ kx) + WLO_OFF, wl[n]);
                }
#pragma unroll
                for (int m = 0; m < 2; m++)
#pragma unroll
                    for (int n = 0; n < 2; n++) mma_bf16(acc[m][n], ah[m], wh[n]);
#pragma unroll
                for (int m = 0; m < 2; m++)
#pragma unroll
                    for (int n = 0; n < 2; n++) mma_bf16(acc[m][n], al[m], wh[n]);
#pragma unroll
                for (int m = 0; m < 2; m++)
#pragma unroll
                    for (int n = 0; n < 2; n++) mma_bf16(acc[m][n], ah[m], wl[n]);
            }
        }
        __syncthreads();   // all warps past this segment's last compute
    }

    // decoder L0 scalar input: GEMM above never needed it — wait only here
    if (J.mode == 1) {
        if (J.pwaitp) wait_ge(J.pwaitp, J.pwaitv);
        if (tid < 128) {
            float s = 0.0f;
            if (J.partin) {
                s = J.fcb[0];
#pragma unroll
                for (int j2 = 0; j2 < NHID; j2++)
                    s += __ldcg(&J.partin[j2 * BB + bm * 128 + tid]);
                if (J.out_s >= 0 && hn == 0) J.outp[(bm * 128 + tid) * HOR + J.out_s] = s;
            }
            xs[tid] = s;
        }
        __syncthreads();
    }

    float* gsm = (float*)dsmem;
    {
        int g = lane >> 2, t4 = lane & 3;
#pragma unroll
        for (int m = 0; m < 2; m++)
#pragma unroll
            for (int n = 0; n < 2; n++) {
                int r0 = wm + m * 16 + g;
                int cc = wn + n * 8 + 2 * t4;
                *(float2*)&gsm[r0 * GPAD + cc]       = make_float2(acc[m][n][0], acc[m][n][1]);
                *(float2*)&gsm[(r0 + 8) * GPAD + cc] = make_float2(acc[m][n][2], acc[m][n][3]);
            }
    }
    __syncthreads();

    const int j   = tid & 15;
    const int col = hn * 16 + j;
    const float bi = J.bias[col];
    const float bf = J.bias[HH + col];
    const float bg = J.bias[2 * HH + col];
    const float bo = J.bias[3 * HH + col];
    float wsi = 0, wsf = 0, wsg = 0, wso = 0;
    if (J.mode == 1) {
        wsi = J.Wscal[col]; wsf = J.Wscal[HH + col];
        wsg = J.Wscal[2 * HH + col]; wso = J.Wscal[3 * HH + col];
    }
    const float fw = (J.mode == 2) ? J.fcW[col] : 0.0f;

#pragma unroll
    for (int i = 0; i < 4; i++) {
        int r = (tid >> 4) + i * 32;
        float pi = gsm[r * GPAD + j]      + bi;
        float pf = gsm[r * GPAD + 16 + j] + bf;
        float pg = gsm[r * GPAD + 32 + j] + bg;
        float po = gsm[r * GPAD + 48 + j] + bo;
        if (J.mode == 1) {
            float xsc = xs[r];
            pi += xsc * wsi; pf += xsc * wsf; pg += xsc * wsg; po += xsc * wso;
        }
        float c = sigmoidf_(pf) * creg[i] + sigmoidf_(pi) * tanhf(pg);
        creg[i] = c;
        float h = sigmoidf_(po) * tanhf(c);
        int idx = (bm * 128 + r) * HH + col;
        __nv_bfloat16 hh = __float2bfloat16(h);
        J.HoutHi[idx] = hh;
        J.HoutLo[idx] = __float2bfloat16(h - __bfloat162float(hh));
        if (J.mode == 2) {
            float p = h * fw;
#pragma unroll
            for (int o = 1; o < 16; o <<= 1) p += __shfl_xor_sync(0xffffffffu, p, o);
            if (j == 0) J.partout[hn * BB + bm * 128 + r] = p;
        }
    }
    // chain_arrive's syncthreads protects gsm/buffers before the next job
}

// ---------------- persistent kernel: two decoupled chains ----------------
__global__ __launch_bounds__(THREADS) void lstm_persist_kernel(
    const float* __restrict__ eb0, const float* __restrict__ eb1,
    const float* __restrict__ db0, const float* __restrict__ db1,
    const float* __restrict__ dWih0, const float* __restrict__ fcW,
    const float* __restrict__ fcb, float* __restrict__ out)
{
    extern __shared__ char dsmem[];
    __shared__ float xs[128];

    const int tid  = threadIdx.x;
    const int wid  = tid >> 5;
    const int lane = tid & 31;
    const int hn   = blockIdx.x;
    const int bm   = blockIdx.y;
    const int z    = blockIdx.z;   // 0: L1 chain, 1: L0 chain

    float* pp[2] = { &g_part[0][0][0], &g_part[1][0][0] };

    float creg[4];
#pragma unroll
    for (int i = 0; i < 4; i++) creg[i] = 0.0f;

    unsigned gen = 0;

    if (z == 1) {
        // ================= L0 chain (64 blocks) =================
#pragma unroll 1
        for (int t = 0; t < TT; t++) {
            JobP J{};
            // seg0: x(t)·Wih0 — x always ready; carries ring backpressure wait
            J.seg[0] = { g_xhi + t * INF, g_xlo + t * INF, TT * INF,
                         g_eWih0_hi, g_eWih0_lo, INF, 1,
                         (t >= 4) ? &g_gen1 : nullptr, (unsigned)(t - 3) };
            // seg1: h0(t-1)·Whh0 — own chain; wait hidden behind seg0
            J.seg[1] = { g_r0hi[(t + 3) & 3], g_r0lo[(t + 3) & 3], HH,
                         g_eWhh0_hi, g_eWhh0_lo, HH, 8,
                         &g_gen0, (unsigned)t };
            J.bias = eb0;
            J.HoutHi = g_r0hi[t & 3]; J.HoutLo = g_r0lo[t & 3];
            J.mode = 0; J.out_s = -1;
            run_job(J, creg, dsmem, xs, tid, wid, lane, hn, bm);
            chain_arrive(&g_cnt0, &g_gen0, gen);    // publishes h0(t): g_gen0 = t+1
        }
        // ---- decoder L0 steps ----
#pragma unroll 1
        for (int s = 0; s < HOR; s++) {
            int u = TT + s;
            JobP J{};
            // seg0 empty; carries ring backpressure wait
            J.seg[0] = { nullptr, nullptr, 0, nullptr, nullptr, 0, 0,
                         &g_gen1, (unsigned)(u - 3) };
            // seg1: h0(u-1)·dWhh0 — own chain
            J.seg[1] = { g_r0hi[(u + 3) & 3], g_r0lo[(u + 3) & 3], HH,
                         g_dWhh0_hi, g_dWhh0_lo, HH, 8,
                         &g_gen0, (unsigned)u };
            J.bias = db0;
            J.HoutHi = g_r0hi[u & 3]; J.HoutLo = g_r0lo[u & 3];
            J.mode = 1;
            J.partin = (s == 0) ? nullptr : pp[(s - 1) & 1];
            J.pwaitp = (s == 0) ? nullptr : &g_gen1;
            J.pwaitv = (unsigned)(TT + s);          // decL1(s-1) done (epilogue dep)
            J.Wscal = dWih0; J.fcb = fcb; J.outp = out; J.out_s = s - 1;
            run_job(J, creg, dsmem, xs, tid, wid, lane, hn, bm);
            chain_arrive(&g_cnt0, &g_gen0, gen);    // g_gen0 = TT + s + 1
        }
        // ---- final output column ----
        if (hn == 0) {
            wait_ge(&g_gen1, (unsigned)(TT + HOR)); // decL1(HOR-1) done
            if (tid < 128) {
                int row = bm * 128 + tid;
                float s = fcb[0];
#pragma unroll
                for (int j2 = 0; j2 < NHID; j2++)
                    s += __ldcg(&pp[(HOR - 1) & 1][j2 * BB + row]);
                out[row * HOR + (HOR - 1)] = s;
            }
        }
    } else {
        // ================= L1 chain (64 blocks) =================
#pragma unroll 1
        for (int t = 0; t < TT; t++) {
            JobP J{};
            // seg0: h0(t)·Wih1 — cross chain (L0 runs ahead). K=512 -> 8 chunks
            J.seg[0] = { g_r0hi[t & 3], g_r0lo[t & 3], HH,
                         g_eWih1_hi, g_eWih1_lo, HH, 8,
                         &g_gen0, (unsigned)(t + 1) };
            // seg1: h1(t-1)·Whh1 — own chain; barrier hidden behind seg0
            J.seg[1] = { g_h1hi[t & 1], g_h1lo[t & 1], HH,
                         g_eWhh1_hi, g_eWhh1_lo, HH, 8,
                         &g_gen1, (unsigned)t };
            J.bias = eb1;
            J.HoutHi = g_h1hi[(t + 1) & 1]; J.HoutLo = g_h1lo[(t + 1) & 1];
            J.mode = 0; J.out_s = -1;
            run_job(J, creg, dsmem, xs, tid, wid, lane, hn, bm);
            chain_arrive(&g_cnt1, &g_gen1, gen);    // g_gen1 = t+1
        }
        // ---- decoder L1 steps ----
#pragma unroll 1
        for (int s = 0; s < HOR; s++) {
            int u = TT + s;
            JobP J{};
            // seg0: h1(u-1)·dWhh1 — own chain (ready early)
            J.seg[0] = { g_h1hi[u & 1], g_h1lo[u & 1], HH,
                         g_dWhh1_hi, g_dWhh1_lo, HH, 8,
                         &g_gen1, (unsigned)u };
            // seg1: h0(u)·dWih1 — cross chain; decL0(s) tail hidden behind seg0
            J.seg[1] = { g_r0hi[u & 3], g_r0lo[u & 3], HH,
                         g_dWih1_hi, g_dWih1_lo, HH, 8,
                         &g_gen0, (unsigned)(u + 1) };
            J.bias = db1;
            J.HoutHi = g_h1hi[(u + 1) & 1]; J.HoutLo = g_h1lo[(u + 1) & 1];
            J.mode = 2; J.out_s = -1;
            J.fcW = fcW; J.partout = pp[s & 1];
            run_job(J, creg, dsmem, xs, tid, wid, lane, hn, bm);
            chain_arrive(&g_cnt1, &g_gen1, gen);    // g_gen1 = TT + s + 1
        }
    }
}

// ---------------- host ----------------
extern "C" void kernel_launch(void* const* d_in, const int* in_sizes, int n_in,
                              void* d_out, int out_size)
{
    const float* x     = (const float*)d_in[0];
    const float* eWih0 = (const float*)d_in[2];
    const float* eWhh0 = (const float*)d_in[3];
    const float* eb0   = (const float*)d_in[4];
    const float* eWih1 = (const float*)d_in[5];
    const float* eWhh1 = (const float*)d_in[6];
    const float* eb1   = (const float*)d_in[7];
    const float* dWih0 = (const float*)d_in[8];
    const float* dWhh0 = (const float*)d_in[9];
    const float* db0   = (const float*)d_in[10];
    const float* dWih1 = (const float*)d_in[11];
    const float* dWhh1 = (const float*)d_in[12];
    const float* db1   = (const float*)d_in[13];
    const float* fcW   = (const float*)d_in[14];
    const float* fcb   = (const float*)d_in[15];
    float* out = (float*)d_out;

    cudaFuncSetAttribute(lstm_persist_kernel,
                         cudaFuncAttributeMaxDynamicSharedMemorySize, DYN_SMEM);

    init_all_kernel<<<256, 256>>>(x, eWih0, eWhh0, eWih1, eWhh1,
                                  dWhh0, dWih1, dWhh1);

    lstm_persist_kernel<<<dim3(NHID, 2, 2), THREADS, DYN_SMEM>>>(
        eb0, eb1, db0, db1, dWih0, fcW, fcb, out);
}

// round 14
// speedup vs baseline: 1.2121x; 1.1679x over previous
#include <cuda_runtime.h>
#include <cuda_bf16.h>
#include <math.h>
#include <stdint.h>

#define BB  256
#define TT  168
#define INF 64
#define HH  512
#define HOR 24
#define NHID 32
#define CHAIN_BLK 128         // blocks per chain barrier
#define THREADS 256
#define MCTA 64               // batch rows per CTA

// ---------------- device scratch (no allocations allowed) ----------------
__device__ __nv_bfloat16 g_xhi[BB * TT * INF], g_xlo[BB * TT * INF];
__device__ __nv_bfloat16 g_r0hi[4][BB * HH], g_r0lo[4][BB * HH];   // h0 ring
__device__ __nv_bfloat16 g_h1hi[2][BB * HH], g_h1lo[2][BB * HH];   // h1 ping-pong
__device__ float g_part[2][NHID][BB];
__device__ unsigned g_cnt0, g_gen0;   // L0 chain barrier (z=1 blocks)
__device__ unsigned g_cnt1, g_gen1;   // L1 chain barrier (z=0 blocks)

__device__ __nv_bfloat16 g_eWih0_hi[2048 * INF], g_eWih0_lo[2048 * INF];
__device__ __nv_bfloat16 g_eWhh0_hi[2048 * HH],  g_eWhh0_lo[2048 * HH];
__device__ __nv_bfloat16 g_eWih1_hi[2048 * HH],  g_eWih1_lo[2048 * HH];
__device__ __nv_bfloat16 g_eWhh1_hi[2048 * HH],  g_eWhh1_lo[2048 * HH];
__device__ __nv_bfloat16 g_dWhh0_hi[2048 * HH],  g_dWhh0_lo[2048 * HH];
__device__ __nv_bfloat16 g_dWih1_hi[2048 * HH],  g_dWih1_lo[2048 * HH];
__device__ __nv_bfloat16 g_dWhh1_hi[2048 * HH],  g_dWhh1_lo[2048 * HH];

__device__ __forceinline__ float sigmoidf_(float x) { return 1.0f / (1.0f + expf(-x)); }

// ---------------- single fused init kernel ----------------
__device__ __forceinline__ void conv_range(const float* __restrict__ s,
                                           __nv_bfloat16* __restrict__ hi,
                                           __nv_bfloat16* __restrict__ lo,
                                           int n, int t0, int stride) {
    for (int i = t0; i < n; i += stride) {
        float v = s[i];
        __nv_bfloat16 h = __float2bfloat16(v);
        hi[i] = h;
        lo[i] = __float2bfloat16(v - __bfloat162float(h));
    }
}

__global__ void init_all_kernel(const float* x,
    const float* eWih0, const float* eWhh0, const float* eWih1, const float* eWhh1,
    const float* dWhh0, const float* dWih1, const float* dWhh1)
{
    int t0 = blockIdx.x * blockDim.x + threadIdx.x;
    int stride = gridDim.x * blockDim.x;
    if (t0 == 0) { g_cnt0 = 0; g_gen0 = 0; g_cnt1 = 0; g_gen1 = 0; }
    __nv_bfloat16 z = __float2bfloat16(0.0f);
    for (int i = t0; i < 4 * BB * HH; i += stride) {
        (&g_r0hi[0][0])[i] = z;
        (&g_r0lo[0][0])[i] = z;
    }
    for (int i = t0; i < 2 * BB * HH; i += stride) {
        (&g_h1hi[0][0])[i] = z;
        (&g_h1lo[0][0])[i] = z;
    }
    conv_range(x,     g_xhi,      g_xlo,      BB * TT * INF, t0, stride);
    conv_range(eWih0, g_eWih0_hi, g_eWih0_lo, 2048 * INF,    t0, stride);
    conv_range(eWhh0, g_eWhh0_hi, g_eWhh0_lo, 2048 * HH,     t0, stride);
    conv_range(eWih1, g_eWih1_hi, g_eWih1_lo, 2048 * HH,     t0, stride);
    conv_range(eWhh1, g_eWhh1_hi, g_eWhh1_lo, 2048 * HH,     t0, stride);
    conv_range(dWhh0, g_dWhh0_hi, g_dWhh0_lo, 2048 * HH,     t0, stride);
    conv_range(dWih1, g_dWih1_hi, g_dWih1_lo, 2048 * HH,     t0, stride);
    conv_range(dWhh1, g_dWhh1_hi, g_dWhh1_lo, 2048 * HH,     t0, stride);
}

// ---------------- PTX helpers ----------------
__device__ __forceinline__ uint32_t smem_u32(const void* p) {
    uint32_t a;
    asm("{ .reg .u64 t; cvta.to.shared.u64 t, %1; cvt.u32.u64 %0, t; }"
        : "=r"(a) : "l"(p));
    return a;
}
__device__ __forceinline__ void cpasync16(uint32_t s, const void* g) {
    asm volatile("cp.async.cg.shared.global [%0], [%1], 16;\n" :: "r"(s), "l"(g));
}
__device__ __forceinline__ void cpasync_commit() {
    asm volatile("cp.async.commit_group;\n");
}
__device__ __forceinline__ void cpasync_wait0() {
    asm volatile("cp.async.wait_group 0;\n");
}
__device__ __forceinline__ void cpasync_wait1() {
    asm volatile("cp.async.wait_group 1;\n");
}
__device__ __forceinline__ void ldm_x4(uint32_t addr, uint32_t r[4]) {
    asm volatile("ldmatrix.sync.aligned.m8n8.x4.shared.b16 {%0,%1,%2,%3}, [%4];"
                 : "=r"(r[0]), "=r"(r[1]), "=r"(r[2]), "=r"(r[3]) : "r"(addr));
}
__device__ __forceinline__ void ldm_x2(uint32_t addr, uint32_t r[2]) {
    asm volatile("ldmatrix.sync.aligned.m8n8.x2.shared.b16 {%0,%1}, [%2];"
                 : "=r"(r[0]), "=r"(r[1]) : "r"(addr));
}
__device__ __forceinline__ void mma_bf16(float d[4], const uint32_t a[4],
                                         const uint32_t b[2]) {
    asm volatile("mma.sync.aligned.m16n8k16.row.col.f32.bf16.bf16.f32 "
                 "{%0,%1,%2,%3}, {%4,%5,%6,%7}, {%8,%9}, {%0,%1,%2,%3};"
                 : "+f"(d[0]), "+f"(d[1]), "+f"(d[2]), "+f"(d[3])
                 : "r"(a[0]), "r"(a[1]), "r"(a[2]), "r"(a[3]),
                   "r"(b[0]), "r"(b[1]));
}

#define SWZ(o) ((o) ^ (((o) >> 3) & 0x70))

// per-chunk buffer: A 64x64 bf16 hi/lo + W 64x64 bf16 hi/lo = 32 KB
#define AHI_OFF 0
#define ALO_OFF 8192
#define WHI_OFF 16384
#define WLO_OFF 24576
#define BUF_BYTES 32768
#define DYN_SMEM (3 * BUF_BYTES)
#define GPAD 80

// ---------------- sync primitives ----------------
__device__ __forceinline__ void chain_arrive(unsigned* cnt, unsigned* gen, unsigned& mygen) {
    mygen++;
    __syncthreads();                            // all threads' epilogue writes issued
    if (threadIdx.x == 0) {
        __threadfence();                        // release
        if (atomicAdd(cnt, 1u) == CHAIN_BLK - 1) {
            *cnt = 0;
            __threadfence();
            *(volatile unsigned*)gen = mygen;
        }
    }
    // no trailing sync: threads run ahead into next step's independent work
}

__device__ __forceinline__ void wait_ge(const unsigned* p, unsigned v) {
    if (threadIdx.x == 0) {
        int it = 0;
        while (*(volatile const unsigned*)p < v) {
            if (++it > 16) __nanosleep(32);
        }
        __threadfence();                        // acquire
    }
    __syncthreads();
}

// ---------------- segment / job descriptors ----------------
struct SegP {
    const __nv_bfloat16 *Ahi, *Alo; int astr;   // activations
    const __nv_bfloat16 *Whi, *Wlo; int wstr;   // weights [2048, wstr]
    int nch;                                    // 64-wide K chunks
    const unsigned* waitp; unsigned waitv;      // producer-readiness wait
};

struct JobP {
    SegP seg[2];
    const float* bias;                    // [2048]
    __nv_bfloat16 *HoutHi, *HoutLo;       // [B*512]
    int mode;                             // 0 plain, 1 dec0, 2 dec1
    const float* partin;                  // dec0 (null for s==0)
    const unsigned* pwaitp; unsigned pwaitv;  // dec0 epilogue-only wait
    const float* Wscal;                   // dec0: dWih0 fp32 [2048]
    const float* fcb;                     // dec0
    float* outp; int out_s;               // dec0
    const float* fcW;                     // dec1
    float* partout;                       // dec1: [NHID][BB]
};

// 32 KB chunk: 2048 16B transfers / 256 threads = 8 iterations.
__device__ __forceinline__ void load_seg_chunk(const SegP& G, int ci, uint32_t sbuf,
                                               int hn, int bm, int tid)
{
    int ko = ci << 6;
#pragma unroll
    for (int it = 0; it < 8; it++) {
        int cc = tid + it * THREADS;
        if (cc < 1024) {                   // W: 2 parts x 64 gate-rows x 8 x 16B
            int p = cc >> 9, r = (cc >> 3) & 63, k16 = cc & 7;
            int gate = r >> 4, j = r & 15;
            const __nv_bfloat16* src = (p ? G.Wlo : G.Whi) +
                (size_t)(gate * HH + hn * 16 + j) * G.wstr + ko + k16 * 8;
            cpasync16(sbuf + (p ? WLO_OFF : WHI_OFF) + SWZ(r * 128 + k16 * 16), src);
        } else {                           // A: 2 parts x 64 rows x 8 x 16B
            int aa = cc - 1024;
            int p = aa >> 9, r = (aa >> 3) & 63, k16 = aa & 7;
            const __nv_bfloat16* src = (p ? G.Alo : G.Ahi) +
                (size_t)(bm * MCTA + r) * G.astr + ko + k16 * 8;
            cpasync16(sbuf + (p ? ALO_OFF : AHI_OFF) + SWZ(r * 128 + k16 * 16), src);
        }
    }
}

// ---------------- one fused LSTM step (2-segment GEMM + epilogue) ----------------
// 256 threads, 8 warps: warp grid 2(M) x 4(N). Warp tile 32 x 16. CTA tile 64 x 64.
__device__ __forceinline__ void run_job(const JobP& J, float* creg,
                                        char* dsmem, float* xs,
                                        int tid, int wid, int lane,
                                        int hn, int bm)
{
    const uint32_t sb = smem_u32(dsmem);
    const int wm = (wid & 1) * 32;        // M offset within 64
    const int wn = (wid >> 1) * 16;       // N offset within 64
    const int a_row_l = (lane & 7) + 8 * ((lane >> 3) & 1);
    const int a_kb_l  = (lane >> 4) * 16;
    const int b_row_l = lane & 7;
    const int b_kb_l  = ((lane >> 3) & 1) * 16;

    float acc[2][2][4];
#pragma unroll
    for (int m = 0; m < 2; m++)
#pragma unroll
        for (int n = 0; n < 2; n++)
#pragma unroll
            for (int e = 0; e < 4; e++) acc[m][n][e] = 0.0f;

#pragma unroll 1
    for (int sgi = 0; sgi < 2; sgi++) {
        const SegP& G = J.seg[sgi];
        if (G.waitp) wait_ge(G.waitp, G.waitv);   // producer-readiness
        const int nch = G.nch;
        if (nch == 0) continue;

        // 3-stage pipeline: up to 2 loads in flight during compute
        load_seg_chunk(G, 0, sb, hn, bm, tid);
        cpasync_commit();
        if (nch > 1) {
            load_seg_chunk(G, 1, sb + BUF_BYTES, hn, bm, tid);
            cpasync_commit();
        }

#pragma unroll 1
        for (int i = 0; i < nch; i++) {
            if (i + 1 < nch) cpasync_wait1(); else cpasync_wait0();
            __syncthreads();          // chunk i visible; all warps past compute(i-1)
            if (i + 2 < nch) {
                load_seg_chunk(G, i + 2,
                               sb + (uint32_t)((i + 2) % 3) * BUF_BYTES, hn, bm, tid);
                cpasync_commit();
            }

            uint32_t buf = sb + (uint32_t)(i % 3) * BUF_BYTES;
            uint32_t aRow[2], bRow[2];
#pragma unroll
            for (int m = 0; m < 2; m++) {
                int row = wm + m * 16 + a_row_l;
                aRow[m] = buf + row * 128 + (((row & 7) << 4) ^ a_kb_l);
            }
#pragma unroll
            for (int n = 0; n < 2; n++) {
                int row = wn + n * 8 + b_row_l;
                bRow[n] = buf + row * 128 + (((row & 7) << 4) ^ b_kb_l);
            }

#pragma unroll
            for (int ks = 0; ks < 4; ks++) {
                uint32_t kx = (uint32_t)(ks * 32);
                uint32_t ah[2][4], al[2][4], wh[2][2], wl[2][2];
#pragma unroll
                for (int m = 0; m < 2; m++) {
                    ldm_x4((aRow[m] ^ kx) + AHI_OFF, ah[m]);
                    ldm_x4((aRow[m] ^ kx) + ALO_OFF, al[m]);
                }
#pragma unroll
                for (int n = 0; n < 2; n++) {
                    ldm_x2((bRow[n] ^ kx) + WHI_OFF, wh[n]);
                    ldm_x2((bRow[n] ^ kx) + WLO_OFF, wl[n]);
                }
#pragma unroll
                for (int m = 0; m < 2; m++)
#pragma unroll
                    for (int n = 0; n < 2; n++) mma_bf16(acc[m][n], ah[m], wh[n]);
#pragma unroll
                for (int m = 0; m < 2; m++)
#pragma unroll
                    for (int n = 0; n < 2; n++) mma_bf16(acc[m][n], al[m], wh[n]);
#pragma unroll
                for (int m = 0; m < 2; m++)
#pragma unroll
                    for (int n = 0; n < 2; n++) mma_bf16(acc[m][n], ah[m], wl[n]);
            }
        }
        __syncthreads();   // all warps past this segment's last compute
    }

    // decoder L0 scalar input: GEMM above never needed it — wait only here
    if (J.mode == 1) {
        if (J.pwaitp) wait_ge(J.pwaitp, J.pwaitv);
        if (tid < MCTA) {
            float s = 0.0f;
            if (J.partin) {
                s = J.fcb[0];
#pragma unroll
                for (int j2 = 0; j2 < NHID; j2++)
                    s += __ldcg(&J.partin[j2 * BB + bm * MCTA + tid]);
                if (J.out_s >= 0 && hn == 0) J.outp[(bm * MCTA + tid) * HOR + J.out_s] = s;
            }
            xs[tid] = s;
        }
        __syncthreads();
    }

    float* gsm = (float*)dsmem;
    {
        int g = lane >> 2, t4 = lane & 3;
#pragma unroll
        for (int m = 0; m < 2; m++)
#pragma unroll
            for (int n = 0; n < 2; n++) {
                int r0 = wm + m * 16 + g;
                int cc = wn + n * 8 + 2 * t4;
                *(float2*)&gsm[r0 * GPAD + cc]       = make_float2(acc[m][n][0], acc[m][n][1]);
                *(float2*)&gsm[(r0 + 8) * GPAD + cc] = make_float2(acc[m][n][2], acc[m][n][3]);
            }
    }
    __syncthreads();

    const int j   = tid & 15;
    const int col = hn * 16 + j;
    const float bi = J.bias[col];
    const float bf = J.bias[HH + col];
    const float bg = J.bias[2 * HH + col];
    const float bo = J.bias[3 * HH + col];
    float wsi = 0, wsf = 0, wsg = 0, wso = 0;
    if (J.mode == 1) {
        wsi = J.Wscal[col]; wsf = J.Wscal[HH + col];
        wsg = J.Wscal[2 * HH + col]; wso = J.Wscal[3 * HH + col];
    }
    const float fw = (J.mode == 2) ? J.fcW[col] : 0.0f;

#pragma unroll
    for (int i = 0; i < 4; i++) {
        int r = (tid >> 4) + i * 16;           // local row 0..63
        float pi = gsm[r * GPAD + j]      + bi;
        float pf = gsm[r * GPAD + 16 + j] + bf;
        float pg = gsm[r * GPAD + 32 + j] + bg;
        float po = gsm[r * GPAD + 48 + j] + bo;
        if (J.mode == 1) {
            float xsc = xs[r];
            pi += xsc * wsi; pf += xsc * wsf; pg += xsc * wsg; po += xsc * wso;
        }
        float c = sigmoidf_(pf) * creg[i] + sigmoidf_(pi) * tanhf(pg);
        creg[i] = c;
        float h = sigmoidf_(po) * tanhf(c);
        int idx = (bm * MCTA + r) * HH + col;
        __nv_bfloat16 hh = __float2bfloat16(h);
        J.HoutHi[idx] = hh;
        J.HoutLo[idx] = __float2bfloat16(h - __bfloat162float(hh));
        if (J.mode == 2) {
            float p = h * fw;
#pragma unroll
            for (int o = 1; o < 16; o <<= 1) p += __shfl_xor_sync(0xffffffffu, p, o);
            if (j == 0) J.partout[hn * BB + bm * MCTA + r] = p;
        }
    }
    // chain_arrive's syncthreads protects gsm/buffers before the next job
}

// ---------------- persistent kernel: two co-located chains ----------------
// grid (32, 4, 2) = 256 blocks, 2 CTAs/SM: z=0 (L1) placed first, z=1 (L0)
// lands as the second CTA on the same SMs — L1 absorbs L0's idle cycles.
__global__ __launch_bounds__(THREADS, 2) void lstm_persist_kernel(
    const float* __restrict__ eb0, const float* __restrict__ eb1,
    const float* __restrict__ db0, const float* __restrict__ db1,
    const float* __restrict__ dWih0, const float* __restrict__ fcW,
    const float* __restrict__ fcb, float* __restrict__ out)
{
    extern __shared__ char dsmem[];
    __shared__ float xs[MCTA];

    const int tid  = threadIdx.x;
    const int wid  = tid >> 5;
    const int lane = tid & 31;
    const int hn   = blockIdx.x;
    const int bm   = blockIdx.y;   // 0..3 (64-row quarters)
    const int z    = blockIdx.z;   // 0: L1 chain, 1: L0 chain

    float* pp[2] = { &g_part[0][0][0], &g_part[1][0][0] };

    float creg[4];
#pragma unroll
    for (int i = 0; i < 4; i++) creg[i] = 0.0f;

    unsigned gen = 0;

    if (z == 1) {
        // ================= L0 chain (128 blocks) =================
#pragma unroll 1
        for (int t = 0; t < TT; t++) {
            JobP J{};
            J.seg[0] = { g_xhi + t * INF, g_xlo + t * INF, TT * INF,
                         g_eWih0_hi, g_eWih0_lo, INF, 1,
                         (t >= 4) ? &g_gen1 : nullptr, (unsigned)(t - 3) };
            J.seg[1] = { g_r0hi[(t + 3) & 3], g_r0lo[(t + 3) & 3], HH,
                         g_eWhh0_hi, g_eWhh0_lo, HH, 8,
                         &g_gen0, (unsigned)t };
            J.bias = eb0;
            J.HoutHi = g_r0hi[t & 3]; J.HoutLo = g_r0lo[t & 3];
            J.mode = 0; J.out_s = -1;
            run_job(J, creg, dsmem, xs, tid, wid, lane, hn, bm);
            chain_arrive(&g_cnt0, &g_gen0, gen);    // publishes h0(t): g_gen0 = t+1
        }
        // ---- decoder L0 steps ----
#pragma unroll 1
        for (int s = 0; s < HOR; s++) {
            int u = TT + s;
            JobP J{};
            J.seg[0] = { nullptr, nullptr, 0, nullptr, nullptr, 0, 0,
                         &g_gen1, (unsigned)(u - 3) };
            J.seg[1] = { g_r0hi[(u + 3) & 3], g_r0lo[(u + 3) & 3], HH,
                         g_dWhh0_hi, g_dWhh0_lo, HH, 8,
                         &g_gen0, (unsigned)u };
            J.bias = db0;
            J.HoutHi = g_r0hi[u & 3]; J.HoutLo = g_r0lo[u & 3];
            J.mode = 1;
            J.partin = (s == 0) ? nullptr : pp[(s - 1) & 1];
            J.pwaitp = (s == 0) ? nullptr : &g_gen1;
            J.pwaitv = (unsigned)(TT + s);
            J.Wscal = dWih0; J.fcb = fcb; J.outp = out; J.out_s = s - 1;
            run_job(J, creg, dsmem, xs, tid, wid, lane, hn, bm);
            chain_arrive(&g_cnt0, &g_gen0, gen);    // g_gen0 = TT + s + 1
        }
        // ---- final output column ----
        if (hn == 0) {
            wait_ge(&g_gen1, (unsigned)(TT + HOR));
            if (tid < MCTA) {
                int row = bm * MCTA + tid;
                float s = fcb[0];
#pragma unroll
                for (int j2 = 0; j2 < NHID; j2++)
                    s += __ldcg(&pp[(HOR - 1) & 1][j2 * BB + row]);
                out[row * HOR + (HOR - 1)] = s;
            }
        }
    } else {
        // ================= L1 chain (128 blocks) =================
#pragma unroll 1
        for (int t = 0; t < TT; t++) {
            JobP J{};
            J.seg[0] = { g_r0hi[t & 3], g_r0lo[t & 3], HH,
                         g_eWih1_hi, g_eWih1_lo, HH, 8,
                         &g_gen0, (unsigned)(t + 1) };
            J.seg[1] = { g_h1hi[t & 1], g_h1lo[t & 1], HH,
                         g_eWhh1_hi, g_eWhh1_lo, HH, 8,
                         &g_gen1, (unsigned)t };
            J.bias = eb1;
            J.HoutHi = g_h1hi[(t + 1) & 1]; J.HoutLo = g_h1lo[(t + 1) & 1];
            J.mode = 0; J.out_s = -1;
            run_job(J, creg, dsmem, xs, tid, wid, lane, hn, bm);
            chain_arrive(&g_cnt1, &g_gen1, gen);    // g_gen1 = t+1
        }
        // ---- decoder L1 steps ----
#pragma unroll 1
        for (int s = 0; s < HOR; s++) {
            int u = TT + s;
            JobP J{};
            J.seg[0] = { g_h1hi[u & 1], g_h1lo[u & 1], HH,
                         g_dWhh1_hi, g_dWhh1_lo, HH, 8,
                         &g_gen1, (unsigned)u };
            J.seg[1] = { g_r0hi[u & 3], g_r0lo[u & 3], HH,
                         g_dWih1_hi, g_dWih1_lo, HH, 8,
                         &g_gen0, (unsigned)(u + 1) };
            J.bias = db1;
            J.HoutHi = g_h1hi[(u + 1) & 1]; J.HoutLo = g_h1lo[(u + 1) & 1];
            J.mode = 2; J.out_s = -1;
            J.fcW = fcW; J.partout = pp[s & 1];
            run_job(J, creg, dsmem, xs, tid, wid, lane, hn, bm);
            chain_arrive(&g_cnt1, &g_gen1, gen);    // g_gen1 = TT + s + 1
        }
    }
}

// ---------------- host ----------------
extern "C" void kernel_launch(void* const* d_in, const int* in_sizes, int n_in,
                              void* d_out, int out_size)
{
    const float* x     = (const float*)d_in[0];
    const float* eWih0 = (const float*)d_in[2];
    const float* eWhh0 = (const float*)d_in[3];
    const float* eb0   = (const float*)d_in[4];
    const float* eWih1 = (const float*)d_in[5];
    const float* eWhh1 = (const float*)d_in[6];
    const float* eb1   = (const float*)d_in[7];
    const float* dWih0 = (const float*)d_in[8];
    const float* dWhh0 = (const float*)d_in[9];
    const float* db0   = (const float*)d_in[10];
    const float* dWih1 = (const float*)d_in[11];
    const float* dWhh1 = (const float*)d_in[12];
    const float* db1   = (const float*)d_in[13];
    const float* fcW   = (const float*)d_in[14];
    const float* fcb   = (const float*)d_in[15];
    float* out = (float*)d_out;

    cudaFuncSetAttribute(lstm_persist_kernel,
                         cudaFuncAttributeMaxDynamicSharedMemorySize, DYN_SMEM);

    init_all_kernel<<<256, 256>>>(x, eWih0, eWhh0, eWih1, eWhh1,
                                  dWhh0, dWih1, dWhh1);

    lstm_persist_kernel<<<dim3(NHID, 4, 2), THREADS, DYN_SMEM>>>(
        eb0, eb1, db0, db1, dWih0, fcW, fcb, out);
}